// round 13
// baseline (speedup 1.0000x reference)
#include <cuda_runtime.h>

// Single-pass inclusive cumsum along leading axis of xs[T, D] (fp32).
// Output: d_out[0:D] = final carry, d_out[D:] = ys[T,D].
//
// Register-staged decoupled lookback:
//  - CTA = 512 threads = 4 row-slices x 128 float4-columns; 8 rows/thread
//    staged in REGISTERS (xs read exactly once, no phase-B re-read).
//  - in-register inclusive prefix; slice totals exchanged via smem
//  - slice-3 thread publishes CTA aggregate, runs per-column epoch-coded
//    lookback (no flag reset needed -> single graph node), broadcasts ex
//  - all threads write v[i] + base from registers with streaming stores.

#define THREADS 512
#define C_F4    128            // float4 columns per CTA
#define SLICES  4
#define RPT     8              // rows per thread
#define ROWS    (SLICES * RPT) // 32 rows per chunk
#define MAX_CHUNKS 512
#define MAX_SP4    2048

static __device__ float4 g_agg4[MAX_CHUNKS * MAX_SP4];
static __device__ float4 g_inc4[MAX_CHUNKS * MAX_SP4];
static __device__ int    g_stat[MAX_CHUNKS * MAX_SP4];  // epoch-coded status

__device__ __forceinline__ int ld_acquire(const int* p) {
    int v;
    asm volatile("ld.acquire.gpu.global.b32 %0, [%1];" : "=r"(v) : "l"(p) : "memory");
    return v;
}
__device__ __forceinline__ void st_release(int* p, int v) {
    asm volatile("st.release.gpu.global.b32 [%0], %1;" :: "l"(p), "r"(v) : "memory");
}
__device__ __forceinline__ float4 f4add(float4 a, float4 b) {
    return make_float4(a.x + b.x, a.y + b.y, a.z + b.z, a.w + b.w);
}

__global__ __launch_bounds__(THREADS, 2)
void scan_lookback(const float4* __restrict__ xs4, float4* __restrict__ ys4,
                   float4* __restrict__ carry4,
                   int stride4, int sp4, int T, int chunks) {
    __shared__ float4 sm_tot[SLICES][C_F4];
    __shared__ float4 sm_ex[C_F4];

    const int g   = blockIdx.x;            // column group
    const int c   = blockIdx.y;            // chunk (x fastest in bid order)
    const int t4  = threadIdx.x & (C_F4 - 1);
    const int s   = threadIdx.x >> 7;      // row slice 0..3
    const int gc4 = g * C_F4 + t4;
    const bool act = gc4 < stride4;

    const int row0 = c * ROWS + s * RPT;
    const float4* xp = xs4 + (size_t)row0 * stride4 + gc4;

    // ---- Load 8 rows into registers (xs read exactly once) ----
    float4 v[RPT];
#pragma unroll
    for (int i = 0; i < RPT; ++i) {
        v[i] = make_float4(0.f, 0.f, 0.f, 0.f);
        if (act && row0 + i < T) v[i] = __ldcs(xp + (size_t)i * stride4);
    }
    // in-register inclusive prefix within the slice
#pragma unroll
    for (int i = 1; i < RPT; ++i) v[i] = f4add(v[i], v[i - 1]);

    sm_tot[s][t4] = v[RPT - 1];
    __syncthreads();

    // exclusive offset of this slice within the chunk
    float4 off = make_float4(0.f, 0.f, 0.f, 0.f);
#pragma unroll
    for (int ss = 0; ss < SLICES - 1; ++ss)
        if (ss < s) off = f4add(off, sm_tot[ss][t4]);

    // ---- Slice-3 thread: publish aggregate + epoch-coded lookback ----
    if (s == SLICES - 1) {
        float4 ex = make_float4(0.f, 0.f, 0.f, 0.f);
        if (act) {
            const float4 agg = f4add(off, v[RPT - 1]);
            const size_t lane = (size_t)c * sp4 + gc4;
            const int e = g_stat[lane] / 2 + 1;   // derive launch epoch
            const int v_agg = 2 * e + 1;
            const int v_inc = 2 * e + 2;
            if (c == 0) {
                g_inc4[lane] = agg;
                st_release(&g_stat[lane], v_inc);
            } else {
                g_agg4[lane] = agg;
                st_release(&g_stat[lane], v_agg);
                int p = c - 1;
                for (;;) {
                    const size_t pl = (size_t)p * sp4 + gc4;
                    int st = ld_acquire(&g_stat[pl]);
                    while (st <= 2 * e) { __nanosleep(32); st = ld_acquire(&g_stat[pl]); }
                    if (st >= v_inc) { ex = f4add(ex, g_inc4[pl]); break; }
                    ex = f4add(ex, g_agg4[pl]);   // st == v_agg
                    --p;
                }
                g_inc4[lane] = f4add(ex, agg);
                st_release(&g_stat[lane], v_inc);
            }
            if (c == chunks - 1)
                carry4[gc4] = f4add(ex, agg);     // final carry
        }
        sm_ex[t4] = ex;
    }
    __syncthreads();

    // ---- Write out from registers (streaming stores) ----
    if (act) {
        const float4 base = f4add(sm_ex[t4], off);
        float4* yp = ys4 + (size_t)row0 * stride4 + gc4;
#pragma unroll
        for (int i = 0; i < RPT; ++i)
            if (row0 + i < T)
                __stcs(yp + (size_t)i * stride4, f4add(v[i], base));
    }
}

// ---------------------------------------------------------------------------
extern "C" void kernel_launch(void* const* d_in, const int* in_sizes, int n_in,
                              void* d_out, int out_size) {
    const float* xs = (const float*)d_in[0];
    float* out = (float*)d_out;

    const int total = in_sizes[0];          // T * D
    int D = out_size - total;
    if (D <= 0 || total % D != 0) D = 4096;
    const int T = total / D;

    const int stride4 = D / 4;
    const int ngroups = (stride4 + C_F4 - 1) / C_F4;
    const int sp4     = ngroups * C_F4;
    const int chunks  = (T + ROWS - 1) / ROWS;   // 256 for T=8192

    float* carry = out;
    float* ys    = out + D;

    dim3 grid(ngroups, chunks);
    scan_lookback<<<grid, THREADS>>>((const float4*)xs, (float4*)ys,
                                     (float4*)carry, stride4, sp4, T, chunks);
}